// round 12
// baseline (speedup 1.0000x reference)
#include <cuda_runtime.h>
#include <cuda_fp16.h>
#include <cstdint>

// ============================================================================
// out[B, OUT] = x[B, IN] @ W[OUT, IN]^T + b[OUT], fp32, 4096^3.
// Plain sm_103 target -> fp16 HMMA single pass (products exact in fp32).
// R12: tile 128x64 with BK=128 (2x64 halves). Tile count 1024->2048 kills the
//      wave-quantization tail (13.5% -> 1.2%) while tensor-work per barrier
//      stays constant (intra-eff preserved). 2 stages x 48KB, 2 CTAs/SM.
// ============================================================================

#define DIM 4096

__device__ __half g_xh[(size_t)DIM * DIM];
__device__ __half g_wh[(size_t)DIM * DIM];

// ----------------------------------------------------------------------------
// helpers
// ----------------------------------------------------------------------------
__device__ __forceinline__ uint32_t smem_u32(const void* p) {
    uint32_t a;
    asm("{ .reg .u64 t; cvta.to.shared.u64 t, %1; cvt.u32.u64 %0, t; }"
        : "=r"(a) : "l"(p));
    return a;
}

__device__ __forceinline__ void cp16(uint32_t dst, const void* src) {
    asm volatile("cp.async.cg.shared.global [%0], [%1], 16;"
                 :: "r"(dst), "l"(src));
}
#define CP_COMMIT() asm volatile("cp.async.commit_group;" ::: "memory")
#define CP_WAIT0()  asm volatile("cp.async.wait_group 0;"  ::: "memory")

__device__ __forceinline__ void ldm4(uint32_t* r, uint32_t addr) {
    asm volatile("ldmatrix.sync.aligned.m8n8.x4.shared.b16 {%0,%1,%2,%3}, [%4];"
                 : "=r"(r[0]), "=r"(r[1]), "=r"(r[2]), "=r"(r[3]) : "r"(addr));
}

__device__ __forceinline__ void mma16816(float* d, const uint32_t* a, const uint32_t* b) {
    asm volatile(
        "mma.sync.aligned.m16n8k16.row.col.f32.f16.f16.f32 "
        "{%0,%1,%2,%3}, {%4,%5,%6,%7}, {%8,%9}, {%0,%1,%2,%3};"
        : "+f"(d[0]), "+f"(d[1]), "+f"(d[2]), "+f"(d[3])
        : "r"(a[0]), "r"(a[1]), "r"(a[2]), "r"(a[3]), "r"(b[0]), "r"(b[1]));
}

// ----------------------------------------------------------------------------
// Kernel 1: fp32 -> fp16 (both matrices in one launch), streaming stores
// ----------------------------------------------------------------------------
__global__ void __launch_bounds__(256)
convert_half(const float* __restrict__ x, const float* __restrict__ W) {
    const int n4 = (DIM * DIM) / 4;
    for (int i = blockIdx.x * blockDim.x + threadIdx.x; i < 2 * n4;
         i += gridDim.x * blockDim.x) {
        const bool isw = i >= n4;
        const int j = isw ? i - n4 : i;
        float4 f = ((const float4*)(isw ? W : x))[j];
        __half2 h0 = __floats2half2_rn(f.x, f.y);
        __half2 h1 = __floats2half2_rn(f.z, f.w);
        uint2 pk;
        pk.x = *(const uint32_t*)&h0;
        pk.y = *(const uint32_t*)&h1;
        __stcs((uint2*)(isw ? g_wh : g_xh) + j, pk);
    }
}

// ----------------------------------------------------------------------------
// Kernel 2: fp16 HMMA GEMM. BM=128 BN=64 BK=128 (two 64-col halves),
// 2 stages, 4 warps (2x2, warp tile 64x32), 2 CTAs/SM.
// All sub-tiles are 128B rows with the proven 8-way XOR swizzle.
// ----------------------------------------------------------------------------
static constexpr int BM = 128;
static constexpr int BN = 64;
static constexpr int BK = 128;                   // as 2 halves of 64
static constexpr int NK = DIM / BK;              // 32 iterations
static constexpr int NTHREADS = 128;

static constexpr int A_HALF = BM * 64 * 2;       // 16384 per K-half
static constexpr int B_HALF = BN * 64 * 2;       // 8192 per K-half
static constexpr int OFF_A = 0;                  // A: half0, half1
static constexpr int OFF_B = 2 * A_HALF;         // B: half0, half1
static constexpr int STAGE_B = 2 * A_HALF + 2 * B_HALF;  // 49152
static constexpr int STAGES = 2;
static constexpr int SMEM_BYTES = STAGES * STAGE_B;      // 98304 -> 2 CTAs/SM

// SW128 swizzle: row r (128B rows), 16B unit u in [0,8)
__device__ __forceinline__ uint32_t sw_off(int r, int u) {
    return (uint32_t)(r * 128 + ((u ^ (r & 7)) << 4));
}

// 3072 cp16 per stage / 128 threads = 24 each (16 for A, 8 for B)
__device__ __forceinline__ void load_stage(uint32_t st, int tm, int tn, int k0, int tid) {
#pragma unroll
    for (int h = 0; h < 2; h++) {
#pragma unroll
        for (int i = 0; i < 8; i++) {
            int c = tid + i * NTHREADS;
            int r = c >> 3, u = c & 7;
            cp16(st + OFF_A + h * A_HALF + sw_off(r, u),
                 g_xh + (size_t)(tm * BM + r) * DIM + k0 + h * 64 + u * 8);
        }
    }
#pragma unroll
    for (int h = 0; h < 2; h++) {
#pragma unroll
        for (int i = 0; i < 4; i++) {
            int c = tid + i * NTHREADS;
            int r = c >> 3, u = c & 7;
            cp16(st + OFF_B + h * B_HALF + sw_off(r, u),
                 g_wh + (size_t)(tn * BN + r) * DIM + k0 + h * 64 + u * 8);
        }
    }
}

__global__ void __launch_bounds__(NTHREADS, 2)
gemm_kernel(const float* __restrict__ bias, float* __restrict__ out) {
    extern __shared__ char smem[];
    const uint32_t sb = smem_u32(smem);
    const int tid = threadIdx.x;
    const int wid = tid >> 5;
    const int lane = tid & 31;
    const int warp_m = wid & 1;      // 2 warps along M (64 rows each)
    const int warp_n = wid >> 1;     // 2 warps along N (32 cols each)

    // Grid: 32 tm x 64 tn = 2048 CTAs, tn-major (consecutive bids share tn).
    const int bid = blockIdx.x;
    const int tm = bid & 31;
    const int tn = bid >> 5;

    // ldmatrix lane addressing, 128B rows (proven fragment map).
    const int a_idx = lane >> 3;
    const int a_row = warp_m * 64 + (lane & 7) + (a_idx & 1) * 8;
    const int a_kk  = a_idx >> 1;
    const int b_idx = lane >> 3;
    const int b_row = warp_n * 32 + (lane & 7) + (b_idx >> 1) * 8;
    const int b_kk  = b_idx & 1;
    const int lsw   = lane & 7;

    uint32_t ua[4], ub[4];
#pragma unroll
    for (int ks = 0; ks < 4; ks++) {
        ua[ks] = (uint32_t)(((ks * 2 + a_kk) ^ lsw) << 4);
        ub[ks] = (uint32_t)(((ks * 2 + b_kk) ^ lsw) << 4);
    }
    const uint32_t a_base = (uint32_t)(a_row * 128);   // + mt*2048
    const uint32_t b_base = (uint32_t)(b_row * 128);   // + p*2048

    float acc[4][4][4];
#pragma unroll
    for (int mt = 0; mt < 4; mt++)
#pragma unroll
        for (int nt = 0; nt < 4; nt++)
#pragma unroll
            for (int j = 0; j < 4; j++) acc[mt][nt][j] = 0.f;

    // Prologue: fill stage 0
    load_stage(sb, tm, tn, 0, tid);
    CP_COMMIT();

    int s_cur = 0;
    for (int kt = 0; kt < NK; kt++) {
        CP_WAIT0();
        __syncthreads();

        // Issue next-stage loads (other buffer; its readers finished at kt-1).
        if (kt + 1 < NK)
            load_stage(sb + (s_cur ^ 1) * STAGE_B, tm, tn, (kt + 1) * BK, tid);
        CP_COMMIT();   // unconditional: keeps wait_group accounting exact

        const uint32_t stg = sb + s_cur * STAGE_B;
#pragma unroll
        for (int h = 0; h < 2; h++) {
            const uint32_t ah_off = stg + OFF_A + h * A_HALF + a_base;
            const uint32_t bh_off = stg + OFF_B + h * B_HALF + b_base;
#pragma unroll
            for (int ks = 0; ks < 4; ks++) {
                uint32_t a[4][4];
#pragma unroll
                for (int mt = 0; mt < 4; mt++)
                    ldm4(a[mt], ah_off + mt * 2048 + ua[ks]);
                uint32_t b[2][4];
#pragma unroll
                for (int p = 0; p < 2; p++)
                    ldm4(b[p], bh_off + p * 2048 + ub[ks]);
#pragma unroll
                for (int mt = 0; mt < 4; mt++) {
#pragma unroll
                    for (int nt = 0; nt < 4; nt++) {
                        const int p = nt >> 1, hc = (nt & 1) * 2;
                        mma16816(acc[mt][nt], a[mt], &b[p][hc]);
                    }
                }
            }
        }

        s_cur ^= 1;
    }

    // Epilogue: add bias, store fp32
    const int m0 = tm * BM + warp_m * 64;
    const int n0 = tn * BN + warp_n * 32;
    const int er = lane >> 2;
    const int ec = (lane & 3) * 2;
#pragma unroll
    for (int nt = 0; nt < 4; nt++) {
        const int col = n0 + nt * 8 + ec;
        const float b0 = __ldg(bias + col);
        const float b1 = __ldg(bias + col + 1);
#pragma unroll
        for (int mt = 0; mt < 4; mt++) {
            const int row = m0 + mt * 16 + er;
            float2 v0 = make_float2(acc[mt][nt][0] + b0, acc[mt][nt][1] + b1);
            float2 v1 = make_float2(acc[mt][nt][2] + b0, acc[mt][nt][3] + b1);
            *(float2*)(out + (size_t)row * DIM + col) = v0;
            *(float2*)(out + (size_t)(row + 8) * DIM + col) = v1;
        }
    }
}

// ----------------------------------------------------------------------------
// kernel_launch
// ----------------------------------------------------------------------------
extern "C" void kernel_launch(void* const* d_in, const int* in_sizes, int n_in,
                              void* d_out, int out_size) {
    const float* x = (const float*)d_in[0];
    const float* W = (const float*)d_in[1];
    const float* b = (const float*)d_in[2];
    float* out = (float*)d_out;

    cudaFuncSetAttribute(gemm_kernel,
                         cudaFuncAttributeMaxDynamicSharedMemorySize, SMEM_BYTES);

    convert_half<<<8192, 256>>>(x, W);

    const int grid = (DIM / BM) * (DIM / BN);   // 32 * 64 = 2048
    gemm_kernel<<<grid, NTHREADS, SMEM_BYTES>>>(b, out);
}

// round 13
// speedup vs baseline: 1.1077x; 1.1077x over previous
#include <cuda_runtime.h>
#include <cuda_fp16.h>
#include <cstdint>

// ============================================================================
// out[B, OUT] = x[B, IN] @ W[OUT, IN]^T + b[OUT], fp32, 4096^3.
// Plain sm_103 target -> fp16 HMMA single pass (products exact in fp32).
// R13: revert GEMM to R10 config (best measured: 302.9us GEMM, tensor 74.4%).
//      Optimize convert: __ldcs/__stcs streaming, branch uniform per block,
//      no grid-stride loop (54% -> ~80% DRAM predicted).
// ============================================================================

#define DIM 4096

__device__ __half g_xh[(size_t)DIM * DIM];
__device__ __half g_wh[(size_t)DIM * DIM];

// ----------------------------------------------------------------------------
// helpers
// ----------------------------------------------------------------------------
__device__ __forceinline__ uint32_t smem_u32(const void* p) {
    uint32_t a;
    asm("{ .reg .u64 t; cvta.to.shared.u64 t, %1; cvt.u32.u64 %0, t; }"
        : "=r"(a) : "l"(p));
    return a;
}

__device__ __forceinline__ void cp16(uint32_t dst, const void* src) {
    asm volatile("cp.async.cg.shared.global [%0], [%1], 16;"
                 :: "r"(dst), "l"(src));
}
#define CP_COMMIT() asm volatile("cp.async.commit_group;" ::: "memory")
#define CP_WAIT()   asm volatile("cp.async.wait_group 1;"  ::: "memory")

__device__ __forceinline__ void ldm4(uint32_t* r, uint32_t addr) {
    asm volatile("ldmatrix.sync.aligned.m8n8.x4.shared.b16 {%0,%1,%2,%3}, [%4];"
                 : "=r"(r[0]), "=r"(r[1]), "=r"(r[2]), "=r"(r[3]) : "r"(addr));
}

__device__ __forceinline__ void mma16816(float* d, const uint32_t* a, const uint32_t* b) {
    asm volatile(
        "mma.sync.aligned.m16n8k16.row.col.f32.f16.f16.f32 "
        "{%0,%1,%2,%3}, {%4,%5,%6,%7}, {%8,%9}, {%0,%1,%2,%3};"
        : "+f"(d[0]), "+f"(d[1]), "+f"(d[2]), "+f"(d[3])
        : "r"(a[0]), "r"(a[1]), "r"(a[2]), "r"(a[3]), "r"(b[0]), "r"(b[1]));
}

// ----------------------------------------------------------------------------
// Kernel 1: fp32 -> fp16. One block = one region (uniform branch), each
// thread converts exactly 2 float4 -> 2 uint2. Streaming loads+stores.
// ----------------------------------------------------------------------------
__global__ void __launch_bounds__(256)
convert_half(const float* __restrict__ x, const float* __restrict__ W) {
    // blocks per matrix: (DIM*DIM/4) float4 / (256 thr * 2) = 8192
    const bool isw = blockIdx.x >= 8192;
    const float4* __restrict__ src = (const float4*)(isw ? W : x);
    uint2* __restrict__ dst = (uint2*)(isw ? g_wh : g_xh);
    const int base = (isw ? blockIdx.x - 8192 : blockIdx.x) * 512 + threadIdx.x;
#pragma unroll
    for (int i = 0; i < 2; i++) {
        const int j = base + i * 256;
        float4 f = __ldcs(src + j);
        __half2 h0 = __floats2half2_rn(f.x, f.y);
        __half2 h1 = __floats2half2_rn(f.z, f.w);
        uint2 pk;
        pk.x = *(const uint32_t*)&h0;
        pk.y = *(const uint32_t*)&h1;
        __stcs(dst + j, pk);
    }
}

// ----------------------------------------------------------------------------
// Kernel 2: fp16 HMMA GEMM. BM=128 BN=128 BK=64, 3 stages, 4 warps (2x2),
// 2 CTAs per SM. Rows are 128B -> full 8-way SW128 swizzle.  (R10 config.)
// ----------------------------------------------------------------------------
static constexpr int BM = 128;
static constexpr int BN = 128;
static constexpr int BK = 64;                    // fp16 elems (128B rows)
static constexpr int NK = DIM / BK;              // 64 iterations
static constexpr int NTHREADS = 128;

static constexpr int A_B = BM * BK * 2;          // 16384
static constexpr int B_B = BN * BK * 2;          // 16384
static constexpr int OFF_A = 0;
static constexpr int OFF_B = A_B;
static constexpr int STAGE_B = A_B + B_B;        // 32768
static constexpr int STAGES = 3;
static constexpr int SMEM_BYTES = STAGES * STAGE_B;  // 98304 -> 2 CTAs/SM

// SW128 swizzle: row r (128B rows), 16B unit u in [0,8)
__device__ __forceinline__ uint32_t sw_off(int r, int u) {
    return (uint32_t)(r * 128 + ((u ^ (r & 7)) << 4));
}

// 2048 cp16 per stage / 128 threads = 16 each (8 for A, 8 for B)
__device__ __forceinline__ void load_stage(uint32_t st, int tm, int tn, int k0, int tid) {
#pragma unroll
    for (int i = 0; i < 8; i++) {
        int c = tid + i * NTHREADS;
        int r = c >> 3, u = c & 7;
        cp16(st + OFF_A + sw_off(r, u),
             g_xh + (size_t)(tm * BM + r) * DIM + k0 + u * 8);
    }
#pragma unroll
    for (int i = 0; i < 8; i++) {
        int c = tid + i * NTHREADS;
        int r = c >> 3, u = c & 7;
        cp16(st + OFF_B + sw_off(r, u),
             g_wh + (size_t)(tn * BN + r) * DIM + k0 + u * 8);
    }
}

__global__ void __launch_bounds__(NTHREADS, 2)
gemm_kernel(const float* __restrict__ bias, float* __restrict__ out) {
    extern __shared__ char smem[];
    const uint32_t sb = smem_u32(smem);
    const int tid = threadIdx.x;
    const int wid = tid >> 5;
    const int lane = tid & 31;
    const int warp_m = wid & 1;      // 2 warps along M (64 rows each)
    const int warp_n = wid >> 1;     // 2 warps along N (64 cols each)

    // Grid: 32 tm x 32 tn = 1024 CTAs, tn-major.
    const int bid = blockIdx.x;
    const int tm = bid & 31;
    const int tn = bid >> 5;

    // ldmatrix lane addressing, 128B rows (proven fragment map).
    const int a_idx = lane >> 3;
    const int a_row = warp_m * 64 + (lane & 7) + (a_idx & 1) * 8;
    const int a_kk  = a_idx >> 1;
    const int b_idx = lane >> 3;
    const int b_row = warp_n * 64 + (lane & 7) + (b_idx >> 1) * 8;
    const int b_kk  = b_idx & 1;
    const int lsw   = lane & 7;

    uint32_t ua[4], ub[4];
#pragma unroll
    for (int ks = 0; ks < 4; ks++) {
        ua[ks] = (uint32_t)(((ks * 2 + a_kk) ^ lsw) << 4);
        ub[ks] = (uint32_t)(((ks * 2 + b_kk) ^ lsw) << 4);
    }
    const uint32_t a_base = (uint32_t)(a_row * 128);   // + mt*2048
    const uint32_t b_base = (uint32_t)(b_row * 128);   // + p*2048

    float acc[4][8][4];
#pragma unroll
    for (int mt = 0; mt < 4; mt++)
#pragma unroll
        for (int nt = 0; nt < 8; nt++)
#pragma unroll
            for (int j = 0; j < 4; j++) acc[mt][nt][j] = 0.f;

    // Prologue: fill STAGES-1 = 2 stages
#pragma unroll
    for (int s = 0; s < STAGES - 1; s++) {
        load_stage(sb + s * STAGE_B, tm, tn, s * BK, tid);
        CP_COMMIT();
    }

    int s_cur = 0;                  // stage of iteration kt
    int s_nxt = STAGES - 1;         // stage receiving kt + STAGES-1
    for (int kt = 0; kt < NK; kt++) {
        CP_WAIT();
        __syncthreads();

        // Issue next-stage loads first (that stage was last read at kt-1;
        // the barrier above makes the overwrite safe).
        const int kn = kt + STAGES - 1;
        if (kn < NK)
            load_stage(sb + s_nxt * STAGE_B, tm, tn, kn * BK, tid);
        CP_COMMIT();   // unconditional: keeps wait_group accounting exact

        const uint32_t stg = sb + s_cur * STAGE_B;
#pragma unroll
        for (int ks = 0; ks < 4; ks++) {
            uint32_t a[4][4];
#pragma unroll
            for (int mt = 0; mt < 4; mt++)
                ldm4(a[mt], stg + OFF_A + a_base + mt * 2048 + ua[ks]);
            uint32_t b[4][4];
#pragma unroll
            for (int p = 0; p < 4; p++)
                ldm4(b[p], stg + OFF_B + b_base + p * 2048 + ub[ks]);
#pragma unroll
            for (int mt = 0; mt < 4; mt++) {
#pragma unroll
                for (int nt = 0; nt < 8; nt++) {
                    const int p = nt >> 1, h = (nt & 1) * 2;
                    mma16816(acc[mt][nt], a[mt], &b[p][h]);
                }
            }
        }

        if (++s_cur == STAGES) s_cur = 0;
        if (++s_nxt == STAGES) s_nxt = 0;
    }

    // Epilogue: add bias, store fp32
    const int m0 = tm * BM + warp_m * 64;
    const int n0 = tn * BN + warp_n * 64;
    const int er = lane >> 2;
    const int ec = (lane & 3) * 2;
#pragma unroll
    for (int nt = 0; nt < 8; nt++) {
        const int col = n0 + nt * 8 + ec;
        const float b0 = __ldg(bias + col);
        const float b1 = __ldg(bias + col + 1);
#pragma unroll
        for (int mt = 0; mt < 4; mt++) {
            const int row = m0 + mt * 16 + er;
            float2 v0 = make_float2(acc[mt][nt][0] + b0, acc[mt][nt][1] + b1);
            float2 v1 = make_float2(acc[mt][nt][2] + b0, acc[mt][nt][3] + b1);
            *(float2*)(out + (size_t)row * DIM + col) = v0;
            *(float2*)(out + (size_t)(row + 8) * DIM + col) = v1;
        }
    }
}

// ----------------------------------------------------------------------------
// kernel_launch
// ----------------------------------------------------------------------------
extern "C" void kernel_launch(void* const* d_in, const int* in_sizes, int n_in,
                              void* d_out, int out_size) {
    const float* x = (const float*)d_in[0];
    const float* W = (const float*)d_in[1];
    const float* b = (const float*)d_in[2];
    float* out = (float*)d_out;

    cudaFuncSetAttribute(gemm_kernel,
                         cudaFuncAttributeMaxDynamicSharedMemorySize, SMEM_BYTES);

    convert_half<<<16384, 256>>>(x, W);

    const int grid = (DIM / BM) * (DIM / BN);   // 32 * 32 = 1024
    gemm_kernel<<<grid, NTHREADS, SMEM_BYTES>>>(b, out);
}